// round 15
// baseline (speedup 1.0000x reference)
#include <cuda_runtime.h>
#include <cstdint>

#define MAXN 10240          // >= 10000 nodes
#define C    128            // channels
#define BF   16             // bond features
#define T    128            // edges per SMEM tile
#define NBLK 456            // 152 SMs * 3 resident blocks
#define RT   16             // output rows per k_out block

// Scratch: __device__ globals.
__device__ __align__(128) float g_accum[MAXN * C];   // scatter-sum target [N, C]
__device__ int   g_deg_row[MAXN];                    // always 0 between runs (k_inv rezeros)
__device__ int   g_deg_col[MAXN];
__device__ float g_inv_row[MAXN];
__device__ float g_inv_col[MAXN];

// ---------------------------------------------------------------------------
// Kernel 0: zero g_accum (pure streaming float4 stores). Keeping this OUT of
// k_out matters: interleaving the rezero with k_out's gather loads measured
// 4x slower (R11/R13 evidence).
// ---------------------------------------------------------------------------
__global__ void k_init(int total4) {
    int i = blockIdx.x * blockDim.x + threadIdx.x;
    if (i < total4) ((float4*)g_accum)[i] = make_float4(0.f, 0.f, 0.f, 0.f);
}

// ---------------------------------------------------------------------------
// Kernel 1: degree histograms. 4 edges per thread via int4 loads.
// deg arrays are guaranteed zero on entry (k_inv rezeros them each run).
// ---------------------------------------------------------------------------
__global__ void k_deg(const int* __restrict__ ei, int E) {
    int t = blockIdx.x * blockDim.x + threadIdx.x;
    int e = t * 4;
    if (e + 3 < E) {
        int4 r = *(const int4*)(ei + e);
        int4 c = *(const int4*)(ei + E + e);
        atomicAdd(&g_deg_row[r.x], 1); atomicAdd(&g_deg_row[r.y], 1);
        atomicAdd(&g_deg_row[r.z], 1); atomicAdd(&g_deg_row[r.w], 1);
        atomicAdd(&g_deg_col[c.x], 1); atomicAdd(&g_deg_col[c.y], 1);
        atomicAdd(&g_deg_col[c.z], 1); atomicAdd(&g_deg_col[c.w], 1);
    } else {
        for (; e < E; ++e) {
            atomicAdd(&g_deg_row[ei[e]], 1);
            atomicAdd(&g_deg_col[ei[E + e]], 1);
        }
    }
}

// ---------------------------------------------------------------------------
// Kernel 2: inv = rsqrt(deg + 1)   (+1 = self-loop seed), then REZERO deg so
// the next graph replay starts from a clean histogram (tiny, harmless here).
// ---------------------------------------------------------------------------
__global__ void k_inv(int N) {
    int i = blockIdx.x * blockDim.x + threadIdx.x;
    if (i >= N) return;
    g_inv_row[i] = rsqrtf((float)(g_deg_row[i] + 1));
    g_inv_col[i] = rsqrtf((float)(g_deg_col[i] + 1));
    g_deg_row[i] = 0;
    g_deg_col[i] = 0;
}

// ---------------------------------------------------------------------------
// SMEM tile of staged edge data (streams decoupled from compute via cp.async)
// ---------------------------------------------------------------------------
struct __align__(16) Tile {
    float attr[T * BF];   // 8192 B
    int   row[T];         // 512 B
    int   col[T];         // 512 B
    float ew[T];          // 512 B
};

__device__ __forceinline__ void cpa16(void* s, const void* g) {
    uint32_t sa = (uint32_t)__cvta_generic_to_shared(s);
    asm volatile("cp.async.cg.shared.global [%0], [%1], 16;" :: "r"(sa), "l"(g) : "memory");
}
__device__ __forceinline__ void cp_commit() {
    asm volatile("cp.async.commit_group;" ::: "memory");
}
__device__ __forceinline__ void cp_wait1() {
    asm volatile("cp.async.wait_group 1;" ::: "memory");
}

// Stage one tile (128 threads cooperate). Fast path uses cp.async; tail path
// plain loads+stores with zero-fill OOB.
__device__ __forceinline__ void stage_tile(
    Tile* t, int base, int E,
    const float* __restrict__ edge_attr,
    const int*   __restrict__ ei,
    const float* __restrict__ ew,
    int tid)
{
    if (base + T <= E && (E & 3) == 0) {
        const float4* asrc = (const float4*)edge_attr + (size_t)base * 4;
        #pragma unroll
        for (int j = 0; j < 4; ++j)
            cpa16(&t->attr[(tid + j * 128) * 4], asrc + tid + j * 128);
        if (tid < 32)        cpa16(&t->row[tid * 4],        ei + base + tid * 4);
        else if (tid < 64)   cpa16(&t->col[(tid - 32) * 4], ei + E + base + (tid - 32) * 4);
        else if (tid < 96)   cpa16(&t->ew [(tid - 64) * 4], ew + base + (tid - 64) * 4);
    } else {
        for (int i = tid; i < T * BF; i += 128) {
            int ge = base + (i >> 4);
            t->attr[i] = (ge < E) ? edge_attr[(size_t)ge * BF + (i & 15)] : 0.f;
        }
        if (tid < T) {
            int ge = base + tid;
            t->row[tid] = (ge < E) ? ei[ge] : 0;
            t->col[tid] = (ge < E) ? ei[E + ge] : 0;
            t->ew[tid]  = (ge < E) ? ew[ge] : 0.f;
        }
    }
}

// ---------------------------------------------------------------------------
// Per-edge compute body (everything needed is in registers/SMEM-broadcast).
// NOTE: the RED deliberately has NO "memory" clobber — g_accum is write-only
// in this kernel, and the clobber was acting as a compiler barrier that
// prevented software-pipelining the next edge's LDS loads across it.
// ---------------------------------------------------------------------------
struct EdgeState {
    int r, c; float w, iv; float4 xv;
};

__device__ __forceinline__ void edge_compute(
    const EdgeState& S, const float* attr_ptr,
    const unsigned long long (&W2)[8][4],
    unsigned long long B0, unsigned long long B1,
    unsigned long long B2, unsigned long long B3,
    int lane)
{
    const ulonglong2* ap = (const ulonglong2*)attr_ptr;   // broadcast LDS.128
    const ulonglong2 q0 = ap[0], q1 = ap[1], q2 = ap[2], q3 = ap[3];

    unsigned long long acc0 = B0, acc1 = B1, acc2 = B2, acc3 = B3;
    #define FF(P, kp) \
        asm("fma.rn.f32x2 %0, %1, %2, %0;" : "+l"(acc0) : "l"(P), "l"(W2[kp][0])); \
        asm("fma.rn.f32x2 %0, %1, %2, %0;" : "+l"(acc1) : "l"(P), "l"(W2[kp][1])); \
        asm("fma.rn.f32x2 %0, %1, %2, %0;" : "+l"(acc2) : "l"(P), "l"(W2[kp][2])); \
        asm("fma.rn.f32x2 %0, %1, %2, %0;" : "+l"(acc3) : "l"(P), "l"(W2[kp][3]));
    FF(q0.x, 0) FF(q0.y, 1) FF(q1.x, 2) FF(q1.y, 3)
    FF(q2.x, 4) FF(q2.y, 5) FF(q3.x, 6) FF(q3.y, 7)
    #undef FF

    float lo0, hi0, lo1, hi1, lo2, hi2, lo3, hi3;
    asm("mov.b64 {%0,%1}, %2;" : "=f"(lo0), "=f"(hi0) : "l"(acc0));
    asm("mov.b64 {%0,%1}, %2;" : "=f"(lo1), "=f"(hi1) : "l"(acc1));
    asm("mov.b64 {%0,%1}, %2;" : "=f"(lo2), "=f"(hi2) : "l"(acc2));
    asm("mov.b64 {%0,%1}, %2;" : "=f"(lo3), "=f"(hi3) : "l"(acc3));

    const float v0 = S.xv.x + (lo0 + hi0);
    const float v1 = S.xv.y + (lo1 + hi1);
    const float v2 = S.xv.z + (lo2 + hi2);
    const float v3 = S.xv.w + (lo3 + hi3);

    const float h  = 0.5f * S.iv * S.w;
    const float t0 = erff(v0 * 0.70710678118654752440f);
    const float t1 = erff(v1 * 0.70710678118654752440f);
    const float t2 = erff(v2 * 0.70710678118654752440f);
    const float t3 = erff(v3 * 0.70710678118654752440f);
    const float vh0 = v0 * h, vh1 = v1 * h, vh2 = v2 * h, vh3 = v3 * h;
    const float m0 = fmaf(vh0, t0, vh0);
    const float m1 = fmaf(vh1, t1, vh1);
    const float m2 = fmaf(vh2, t2, vh2);
    const float m3 = fmaf(vh3, t3, vh3);

    float* dst = &g_accum[(size_t)S.c * C + lane * 4];
    asm volatile("red.global.add.v4.f32 [%0], {%1, %2, %3, %4};"
                 :: "l"(dst), "f"(m0), "f"(m1), "f"(m2), "f"(m3));
}

// ---------------------------------------------------------------------------
// Kernel 3: persistent tiled message kernel (real edges only; self-loops are
// folded into k_out). Double-buffered cp.async staging + depth-2 x-gather
// register pipeline; RED without compiler barrier so the unrolled body
// pipelines LDS/compute across edges.  (UNCHANGED from R13 — ~106 us.)
// ---------------------------------------------------------------------------
__global__ __launch_bounds__(128, 3) void k_msg(
    const float* __restrict__ x,
    const float* __restrict__ edge_attr,
    const float* __restrict__ ew,
    const float* __restrict__ Wb,
    const float* __restrict__ bb,
    const int*   __restrict__ ei,
    int E)
{
    __shared__ Tile tiles[2];

    const int tid  = threadIdx.x;
    const int lane = tid & 31;
    const int warp = tid >> 5;
    const int ntiles = (E + T - 1) / T;
    const int t0 = blockIdx.x;
    if (t0 >= ntiles) return;

    // --- per-warp W_bond slice in registers, k-pair packed for FFMA2 ---
    unsigned long long W2[8][4];
    #pragma unroll
    for (int kp = 0; kp < 8; ++kp) {
        const float4 ra = __ldg((const float4*)Wb + (2*kp)   * 32 + lane);
        const float4 rb = __ldg((const float4*)Wb + (2*kp+1) * 32 + lane);
        asm("mov.b64 %0,{%1,%2};" : "=l"(W2[kp][0]) : "f"(ra.x), "f"(rb.x));
        asm("mov.b64 %0,{%1,%2};" : "=l"(W2[kp][1]) : "f"(ra.y), "f"(rb.y));
        asm("mov.b64 %0,{%1,%2};" : "=l"(W2[kp][2]) : "f"(ra.z), "f"(rb.z));
        asm("mov.b64 %0,{%1,%2};" : "=l"(W2[kp][3]) : "f"(ra.w), "f"(rb.w));
    }
    unsigned long long B0, B1, B2, B3;      // {bias, 0} accumulator seeds
    {
        const float4 bv = __ldg((const float4*)bb + lane);
        const float z = 0.0f;
        asm("mov.b64 %0,{%1,%2};" : "=l"(B0) : "f"(bv.x), "f"(z));
        asm("mov.b64 %0,{%1,%2};" : "=l"(B1) : "f"(bv.y), "f"(z));
        asm("mov.b64 %0,{%1,%2};" : "=l"(B2) : "f"(bv.z), "f"(z));
        asm("mov.b64 %0,{%1,%2};" : "=l"(B3) : "f"(bv.w), "f"(z));
    }

    // --- prologue: stage first two tiles ---
    stage_tile(&tiles[0], t0 * T, E, edge_attr, ei, ew, tid);
    cp_commit();
    {
        const int t1 = t0 + gridDim.x;
        if (t1 < ntiles) stage_tile(&tiles[1], t1 * T, E, edge_attr, ei, ew, tid);
    }
    cp_commit();

    int buf = 0;
    for (int tt = t0; tt < ntiles; tt += gridDim.x) {
        cp_wait1();
        __syncthreads();
        const Tile* tp = &tiles[buf];
        const int base = tt * T;
        const int le0 = warp * 32;       // this warp's 32 edges in the tile
        const int nv  = E - base - le0;  // #valid edges for this warp

        // depth-2 x-gather pipeline
        EdgeState A, Bs;
        A.r  = tp->row[le0];     A.c  = tp->col[le0];     A.w  = tp->ew[le0];
        Bs.r = tp->row[le0 + 1]; Bs.c = tp->col[le0 + 1]; Bs.w = tp->ew[le0 + 1];
        A.xv  = __ldg((const float4*)x + A.r * 32 + lane);
        A.iv  = __ldg(g_inv_row + A.r) * __ldg(g_inv_col + A.c);
        Bs.xv = __ldg((const float4*)x + Bs.r * 32 + lane);
        Bs.iv = __ldg(g_inv_row + Bs.r) * __ldg(g_inv_col + Bs.c);

        if (nv >= 32) {
            // full tile for this warp: no per-edge bounds checks
            #pragma unroll 4
            for (int i = 0; i < 32; ++i) {
                EdgeState Cs;
                if (i + 2 < 32) {
                    Cs.r = tp->row[le0 + i + 2];
                    Cs.c = tp->col[le0 + i + 2];
                    Cs.w = tp->ew [le0 + i + 2];
                    Cs.xv = __ldg((const float4*)x + Cs.r * 32 + lane);
                    Cs.iv = __ldg(g_inv_row + Cs.r) * __ldg(g_inv_col + Cs.c);
                }
                edge_compute(A, tp->attr + (le0 + i) * BF, W2, B0, B1, B2, B3, lane);
                A = Bs; Bs = Cs;
            }
        } else {
            #pragma unroll 4
            for (int i = 0; i < 32; ++i) {
                EdgeState Cs;
                if (i + 2 < 32) {
                    Cs.r = tp->row[le0 + i + 2];
                    Cs.c = tp->col[le0 + i + 2];
                    Cs.w = tp->ew [le0 + i + 2];
                    Cs.xv = __ldg((const float4*)x + Cs.r * 32 + lane);
                    Cs.iv = __ldg(g_inv_row + Cs.r) * __ldg(g_inv_col + Cs.c);
                }
                if (i < nv)
                    edge_compute(A, tp->attr + (le0 + i) * BF, W2, B0, B1, B2, B3, lane);
                A = Bs; Bs = Cs;
            }
        }

        __syncthreads();
        const int tn = tt + 2 * gridDim.x;
        if (tn < ntiles) stage_tile(&tiles[buf], tn * T, E, edge_attr, ei, ew, tid);
        cp_commit();
        buf ^= 1;
    }
}

// ---------------------------------------------------------------------------
// Kernel 4: out = (g_accum + selfloop_msg) @ W_lin + b_lin, register-tiled.
// NO rezero store here (that was the R11/R13 regression).
// Block = 128 threads computes a 16x128 output tile; thread owns a 4x4
// micro-tile. Inner loop: 4x LDS.128 + 4x LDG.128 (coalesced) + 64 FMA.
// ---------------------------------------------------------------------------
__global__ __launch_bounds__(128) void k_out(
    const float* __restrict__ Wl,
    const float* __restrict__ bl,
    const float* __restrict__ x,
    float* __restrict__ out,
    int N)
{
    __shared__ __align__(16) float sx[RT][C];   // 8 KB
    const int tid = threadIdx.x;
    const int n0  = blockIdx.x * RT;

    // --- stage sx = g_accum + selfloop (gelu(x)*inv_r*inv_c, ew=1) ---
    #pragma unroll
    for (int it = 0; it < RT; ++it) {
        const int i = tid + it * 128;          // RT*C/128 = 16 elements/thread
        const int r = i >> 7, j = i & 127;
        const int n = n0 + r;
        if (n < N) {
            const float v = x[(size_t)n * C + j];
            const float g = 0.5f * v * (1.0f + erff(v * 0.70710678118654752440f));
            const float iv = g_inv_row[n] * g_inv_col[n];
            sx[r][j] = g_accum[(size_t)n * C + j] + g * iv;
        } else {
            sx[r][j] = 0.0f;
        }
    }
    __syncthreads();

    const int rg = tid >> 5;          // row group: 4 rows starting at 4*rg
    const int jg = tid & 31;          // col group: 4 cols starting at 4*jg
    const int r0 = rg * 4;

    float acc[4][4];
    #pragma unroll
    for (int a = 0; a < 4; ++a)
        #pragma unroll
        for (int b = 0; b < 4; ++b) acc[a][b] = 0.0f;

    #pragma unroll 4
    for (int c = 0; c < C; c += 4) {
        const float4 s0 = *(const float4*)&sx[r0 + 0][c];
        const float4 s1 = *(const float4*)&sx[r0 + 1][c];
        const float4 s2 = *(const float4*)&sx[r0 + 2][c];
        const float4 s3 = *(const float4*)&sx[r0 + 3][c];
        const float4 w0 = __ldg((const float4*)(Wl + (c + 0) * C) + jg);
        const float4 w1 = __ldg((const float4*)(Wl + (c + 1) * C) + jg);
        const float4 w2 = __ldg((const float4*)(Wl + (c + 2) * C) + jg);
        const float4 w3 = __ldg((const float4*)(Wl + (c + 3) * C) + jg);

        #define ROW(a, sv) \
            acc[a][0] = fmaf(sv.x, w0.x, acc[a][0]); acc[a][1] = fmaf(sv.x, w0.y, acc[a][1]); \
            acc[a][2] = fmaf(sv.x, w0.z, acc[a][2]); acc[a][3] = fmaf(sv.x, w0.w, acc[a][3]); \
            acc[a][0] = fmaf(sv.y, w1.x, acc[a][0]); acc[a][1] = fmaf(sv.y, w1.y, acc[a][1]); \
            acc[a][2] = fmaf(sv.y, w1.z, acc[a][2]); acc[a][3] = fmaf(sv.y, w1.w, acc[a][3]); \
            acc[a][0] = fmaf(sv.z, w2.x, acc[a][0]); acc[a][1] = fmaf(sv.z, w2.y, acc[a][1]); \
            acc[a][2] = fmaf(sv.z, w2.z, acc[a][2]); acc[a][3] = fmaf(sv.z, w2.w, acc[a][3]); \
            acc[a][0] = fmaf(sv.w, w3.x, acc[a][0]); acc[a][1] = fmaf(sv.w, w3.y, acc[a][1]); \
            acc[a][2] = fmaf(sv.w, w3.z, acc[a][2]); acc[a][3] = fmaf(sv.w, w3.w, acc[a][3]);
        ROW(0, s0) ROW(1, s1) ROW(2, s2) ROW(3, s3)
        #undef ROW
    }

    const float4 bv = __ldg((const float4*)bl + jg);
    #pragma unroll
    for (int a = 0; a < 4; ++a) {
        const int n = n0 + r0 + a;
        if (n < N) {
            float4 o;
            o.x = acc[a][0] + bv.x;
            o.y = acc[a][1] + bv.y;
            o.z = acc[a][2] + bv.z;
            o.w = acc[a][3] + bv.w;
            *((float4*)(out + (size_t)n * C) + jg) = o;
        }
    }
}

// ---------------------------------------------------------------------------
// Launch: 5-kernel chain. k_init restored (dedicated streaming zero of
// g_accum) — interleaving the rezero inside k_out was the R11/R13 regression.
// ---------------------------------------------------------------------------
extern "C" void kernel_launch(void* const* d_in, const int* in_sizes, int n_in,
                              void* d_out, int out_size)
{
    const float* x         = (const float*)d_in[0];   // [N, 128]
    const float* edge_attr = (const float*)d_in[1];   // [E, 16]
    const float* ew        = (const float*)d_in[2];   // [E, 1]
    const float* Wb        = (const float*)d_in[3];   // [16, 128]
    const float* bb        = (const float*)d_in[4];   // [128]
    const float* Wl        = (const float*)d_in[5];   // [128, 128]
    const float* bl        = (const float*)d_in[6];   // [128]
    const int*   ei        = (const int*)d_in[7];     // [2, E]
    float*       out       = (float*)d_out;           // [N, 128]

    const int E = in_sizes[2];          // edge_weight element count
    const int N = in_sizes[0] / C;      // x rows

    {   // zero the accumulator (streaming float4)
        int total4 = N * (C / 4);
        int threads = 256;
        int blocks = (total4 + threads - 1) / threads;
        k_init<<<blocks, threads>>>(total4);
    }
    {
        int threads = 256;
        int work = (E + 3) / 4;
        int blocks = (work + threads - 1) / threads;
        k_deg<<<blocks, threads>>>(ei, E);
    }
    {
        int threads = 256;
        int blocks = (N + threads - 1) / threads;
        k_inv<<<blocks, threads>>>(N);
    }
    {
        int ntiles = (E + T - 1) / T;
        int blocks = (ntiles < NBLK) ? ntiles : NBLK;
        k_msg<<<blocks, 128>>>(x, edge_attr, ew, Wb, bb, ei, E);
    }
    {
        int blocks = (N + RT - 1) / RT;
        k_out<<<blocks, 128>>>(Wl, bl, x, out, N);
    }
}

// round 16
// speedup vs baseline: 1.5436x; 1.5436x over previous
#include <cuda_runtime.h>
#include <cstdint>

#define MAXN 10240          // >= 10000 nodes
#define C    128            // channels
#define BF   16             // bond features
#define T    128            // edges per SMEM tile
#define NBLK 456            // 152 SMs * 3 resident blocks
#define RT   16             // output rows per k_out block

// Scratch: __device__ globals (no allocation allowed).
__device__ __align__(128) float g_accum[MAXN * C];   // scatter-sum target [N, C]
__device__ int   g_deg_row[MAXN];
__device__ int   g_deg_col[MAXN];
__device__ float g_inv_row[MAXN];
__device__ float g_inv_col[MAXN];

// ---------------------------------------------------------------------------
// Kernel 1: zero accumulator (float4), init degrees to 1 (self-loop count).
// (R10-verbatim)
// ---------------------------------------------------------------------------
__global__ void k_init(int N) {
    int i = blockIdx.x * blockDim.x + threadIdx.x;
    if (i < N * (C / 4)) ((float4*)g_accum)[i] = make_float4(0.f, 0.f, 0.f, 0.f);
    if (i < N) { g_deg_row[i] = 1; g_deg_col[i] = 1; }
}

// ---------------------------------------------------------------------------
// Kernel 2: degree histograms. 4 edges per thread via int4 loads.
// (R10-verbatim)
// ---------------------------------------------------------------------------
__global__ void k_deg(const int* __restrict__ ei, int E) {
    int t = blockIdx.x * blockDim.x + threadIdx.x;
    int e = t * 4;
    if (e + 3 < E) {
        int4 r = *(const int4*)(ei + e);
        int4 c = *(const int4*)(ei + E + e);
        atomicAdd(&g_deg_row[r.x], 1); atomicAdd(&g_deg_row[r.y], 1);
        atomicAdd(&g_deg_row[r.z], 1); atomicAdd(&g_deg_row[r.w], 1);
        atomicAdd(&g_deg_col[c.x], 1); atomicAdd(&g_deg_col[c.y], 1);
        atomicAdd(&g_deg_col[c.z], 1); atomicAdd(&g_deg_col[c.w], 1);
    } else {
        for (; e < E; ++e) {
            atomicAdd(&g_deg_row[ei[e]], 1);
            atomicAdd(&g_deg_col[ei[E + e]], 1);
        }
    }
}

// ---------------------------------------------------------------------------
// Kernel 3: inverse-sqrt degree tables. deg >= 1 always (self-loops).
// (R10-verbatim)
// ---------------------------------------------------------------------------
__global__ void k_inv(int N) {
    int i = blockIdx.x * blockDim.x + threadIdx.x;
    if (i >= N) return;
    g_inv_row[i] = rsqrtf((float)g_deg_row[i]);
    g_inv_col[i] = rsqrtf((float)g_deg_col[i]);
}

// ---------------------------------------------------------------------------
// SMEM tile of staged edge data (streams decoupled from compute via cp.async)
// ---------------------------------------------------------------------------
struct __align__(16) Tile {
    float attr[T * BF];   // 8192 B
    int   row[T];         // 512 B
    int   col[T];         // 512 B
    float ew[T];          // 512 B
};

__device__ __forceinline__ void cpa16(void* s, const void* g) {
    uint32_t sa = (uint32_t)__cvta_generic_to_shared(s);
    asm volatile("cp.async.cg.shared.global [%0], [%1], 16;" :: "r"(sa), "l"(g) : "memory");
}
__device__ __forceinline__ void cp_commit() {
    asm volatile("cp.async.commit_group;" ::: "memory");
}
__device__ __forceinline__ void cp_wait1() {
    asm volatile("cp.async.wait_group 1;" ::: "memory");
}

// Stage one tile (128 threads cooperate). Fast path uses cp.async; tail path
// plain loads+stores with zero-fill OOB. (R10-verbatim)
__device__ __forceinline__ void stage_tile(
    Tile* t, int base, int E,
    const float* __restrict__ edge_attr,
    const int*   __restrict__ ei,
    const float* __restrict__ ew,
    int tid)
{
    if (base + T <= E && (E & 3) == 0) {
        const float4* asrc = (const float4*)edge_attr + (size_t)base * 4;
        #pragma unroll
        for (int j = 0; j < 4; ++j)
            cpa16(&t->attr[(tid + j * 128) * 4], asrc + tid + j * 128);
        if (tid < 32)        cpa16(&t->row[tid * 4],        ei + base + tid * 4);
        else if (tid < 64)   cpa16(&t->col[(tid - 32) * 4], ei + E + base + (tid - 32) * 4);
        else if (tid < 96)   cpa16(&t->ew [(tid - 64) * 4], ew + base + (tid - 64) * 4);
    } else {
        for (int i = tid; i < T * BF; i += 128) {
            int ge = base + (i >> 4);
            t->attr[i] = (ge < E) ? edge_attr[(size_t)ge * BF + (i & 15)] : 0.f;
        }
        if (tid < T) {
            int ge = base + tid;
            t->row[tid] = (ge < E) ? ei[ge] : 0;
            t->col[tid] = (ge < E) ? ei[E + ge] : 0;
            t->ew[tid]  = (ge < E) ? ew[ge] : 0.f;
        }
    }
}

// ---------------------------------------------------------------------------
// Kernel 4: persistent tiled message kernel — R10-VERBATIM (the validated
// 153.7us configuration: RED keeps its "memory" clobber, inline edge body,
// explicit pipeline locals, single loop with per-edge nv guard).
// ---------------------------------------------------------------------------
__global__ __launch_bounds__(128, 3) void k_msg(
    const float* __restrict__ x,
    const float* __restrict__ edge_attr,
    const float* __restrict__ ew,
    const float* __restrict__ Wb,
    const float* __restrict__ bb,
    const int*   __restrict__ ei,
    int E)
{
    __shared__ Tile tiles[2];

    const int tid  = threadIdx.x;
    const int lane = tid & 31;
    const int warp = tid >> 5;
    const int ntiles = (E + T - 1) / T;
    const int t0 = blockIdx.x;
    if (t0 >= ntiles) return;

    // --- per-warp W_bond slice in registers, k-pair packed ---
    unsigned long long W2[8][4];
    #pragma unroll
    for (int kp = 0; kp < 8; ++kp) {
        const float4 ra = __ldg((const float4*)Wb + (2*kp)   * 32 + lane);
        const float4 rb = __ldg((const float4*)Wb + (2*kp+1) * 32 + lane);
        asm("mov.b64 %0,{%1,%2};" : "=l"(W2[kp][0]) : "f"(ra.x), "f"(rb.x));
        asm("mov.b64 %0,{%1,%2};" : "=l"(W2[kp][1]) : "f"(ra.y), "f"(rb.y));
        asm("mov.b64 %0,{%1,%2};" : "=l"(W2[kp][2]) : "f"(ra.z), "f"(rb.z));
        asm("mov.b64 %0,{%1,%2};" : "=l"(W2[kp][3]) : "f"(ra.w), "f"(rb.w));
    }
    unsigned long long B0, B1, B2, B3;      // {bias, 0} accumulator seeds
    {
        const float4 bv = __ldg((const float4*)bb + lane);
        const float z = 0.0f;
        asm("mov.b64 %0,{%1,%2};" : "=l"(B0) : "f"(bv.x), "f"(z));
        asm("mov.b64 %0,{%1,%2};" : "=l"(B1) : "f"(bv.y), "f"(z));
        asm("mov.b64 %0,{%1,%2};" : "=l"(B2) : "f"(bv.z), "f"(z));
        asm("mov.b64 %0,{%1,%2};" : "=l"(B3) : "f"(bv.w), "f"(z));
    }

    // --- prologue: stage first two tiles ---
    stage_tile(&tiles[0], t0 * T, E, edge_attr, ei, ew, tid);
    cp_commit();
    {
        const int t1 = t0 + gridDim.x;
        if (t1 < ntiles) stage_tile(&tiles[1], t1 * T, E, edge_attr, ei, ew, tid);
    }
    cp_commit();

    int buf = 0;
    for (int tt = t0; tt < ntiles; tt += gridDim.x) {
        cp_wait1();                 // tile tt staged (own copies done)
        __syncthreads();            // visible to all warps
        const Tile* tp = &tiles[buf];
        const int base = tt * T;
        const int le0 = warp * 32;  // this warp's 32 edges within the tile
        const int nv = E - base - le0;   // #valid edges for this warp (may be <=0)

        // --- depth-2 x-gather pipeline over the warp's 32 edges ---
        int   rA = tp->row[le0],     cA = tp->col[le0];     float wA = tp->ew[le0];
        int   rB = tp->row[le0 + 1], cB = tp->col[le0 + 1]; float wB = tp->ew[le0 + 1];
        float4 xA = __ldg((const float4*)x + rA * 32 + lane);
        float  ivA = __ldg(g_inv_row + rA) * __ldg(g_inv_col + cA);
        float4 xB = __ldg((const float4*)x + rB * 32 + lane);
        float  ivB = __ldg(g_inv_row + rB) * __ldg(g_inv_col + cB);

        #pragma unroll 4
        for (int i = 0; i < 32; ++i) {
            // prefetch edge i+2
            int rC = 0, cC = 0; float wC = 0.f; float ivC = 0.f;
            float4 xC = make_float4(0.f, 0.f, 0.f, 0.f);
            if (i + 2 < 32) {
                rC = tp->row[le0 + i + 2];
                cC = tp->col[le0 + i + 2];
                wC = tp->ew [le0 + i + 2];
                xC  = __ldg((const float4*)x + rC * 32 + lane);
                ivC = __ldg(g_inv_row + rC) * __ldg(g_inv_col + cC);
            }

            if (i < nv) {
                // attr: broadcast LDS.128 -> FFMA2 operand pairs directly
                const ulonglong2* ap = (const ulonglong2*)(tp->attr + (le0 + i) * BF);
                const ulonglong2 q0 = ap[0], q1 = ap[1], q2 = ap[2], q3 = ap[3];
                const unsigned long long P[8] =
                    {q0.x, q0.y, q1.x, q1.y, q2.x, q2.y, q3.x, q3.y};

                unsigned long long acc0 = B0, acc1 = B1, acc2 = B2, acc3 = B3;
                #pragma unroll
                for (int kp = 0; kp < 8; ++kp) {
                    asm("fma.rn.f32x2 %0, %1, %2, %0;" : "+l"(acc0) : "l"(P[kp]), "l"(W2[kp][0]));
                    asm("fma.rn.f32x2 %0, %1, %2, %0;" : "+l"(acc1) : "l"(P[kp]), "l"(W2[kp][1]));
                    asm("fma.rn.f32x2 %0, %1, %2, %0;" : "+l"(acc2) : "l"(P[kp]), "l"(W2[kp][2]));
                    asm("fma.rn.f32x2 %0, %1, %2, %0;" : "+l"(acc3) : "l"(P[kp]), "l"(W2[kp][3]));
                }
                float lo0, hi0, lo1, hi1, lo2, hi2, lo3, hi3;
                asm("mov.b64 {%0,%1}, %2;" : "=f"(lo0), "=f"(hi0) : "l"(acc0));
                asm("mov.b64 {%0,%1}, %2;" : "=f"(lo1), "=f"(hi1) : "l"(acc1));
                asm("mov.b64 {%0,%1}, %2;" : "=f"(lo2), "=f"(hi2) : "l"(acc2));
                asm("mov.b64 {%0,%1}, %2;" : "=f"(lo3), "=f"(hi3) : "l"(acc3));

                const float v0 = xA.x + (lo0 + hi0);
                const float v1 = xA.y + (lo1 + hi1);
                const float v2 = xA.z + (lo2 + hi2);
                const float v3 = xA.w + (lo3 + hi3);

                const float h = 0.5f * ivA * wA;
                const float tt0 = erff(v0 * 0.70710678118654752440f);
                const float tt1 = erff(v1 * 0.70710678118654752440f);
                const float tt2 = erff(v2 * 0.70710678118654752440f);
                const float tt3 = erff(v3 * 0.70710678118654752440f);
                const float vh0 = v0 * h, vh1 = v1 * h, vh2 = v2 * h, vh3 = v3 * h;
                const float m0 = fmaf(vh0, tt0, vh0);
                const float m1 = fmaf(vh1, tt1, vh1);
                const float m2 = fmaf(vh2, tt2, vh2);
                const float m3 = fmaf(vh3, tt3, vh3);

                float* dst = &g_accum[(size_t)cA * C + lane * 4];
                asm volatile("red.global.add.v4.f32 [%0], {%1, %2, %3, %4};"
                             :: "l"(dst), "f"(m0), "f"(m1), "f"(m2), "f"(m3) : "memory");
            }

            // rotate (renamed away under unroll)
            rA = rB; cA = cB; wA = wB; xA = xB; ivA = ivB;
            rB = rC; cB = cC; wB = wC; xB = xC; ivB = ivC;
        }

        __syncthreads();            // all warps done reading tiles[buf]
        const int tn = tt + 2 * gridDim.x;
        if (tn < ntiles) stage_tile(&tiles[buf], tn * T, E, edge_attr, ei, ew, tid);
        cp_commit();                // exactly one group per iteration
        buf ^= 1;
    }
}

// ---------------------------------------------------------------------------
// Kernel 5: out = (g_accum + selfloop_msg) @ W_lin + b_lin, register-tiled.
// (The ONE change vs the R10 champion. NO rezero store — that was the
// R11/R13 poison.) Block = 128 threads computes a 16x128 output tile;
// thread owns a 4x4 micro-tile: 4x LDS.128 + 4x LDG.128 per 64 FMA.
// ---------------------------------------------------------------------------
__global__ __launch_bounds__(128) void k_out(
    const float* __restrict__ Wl,
    const float* __restrict__ bl,
    const float* __restrict__ x,
    float* __restrict__ out,
    int N)
{
    __shared__ __align__(16) float sx[RT][C];   // 8 KB
    const int tid = threadIdx.x;
    const int n0  = blockIdx.x * RT;

    // --- stage sx = g_accum + selfloop (gelu(x)*inv_r*inv_c, ew=1) ---
    #pragma unroll
    for (int it = 0; it < RT; ++it) {
        const int i = tid + it * 128;          // RT*C/128 = 16 elements/thread
        const int r = i >> 7, j = i & 127;
        const int n = n0 + r;
        if (n < N) {
            const float v = x[(size_t)n * C + j];
            const float g = 0.5f * v * (1.0f + erff(v * 0.70710678118654752440f));
            const float iv = g_inv_row[n] * g_inv_col[n];
            sx[r][j] = g_accum[(size_t)n * C + j] + g * iv;
        } else {
            sx[r][j] = 0.0f;
        }
    }
    __syncthreads();

    const int rg = tid >> 5;          // row group: 4 rows starting at 4*rg
    const int jg = tid & 31;          // col group: 4 cols starting at 4*jg
    const int r0 = rg * 4;

    float acc[4][4];
    #pragma unroll
    for (int a = 0; a < 4; ++a)
        #pragma unroll
        for (int b = 0; b < 4; ++b) acc[a][b] = 0.0f;

    #pragma unroll 4
    for (int c = 0; c < C; c += 4) {
        const float4 s0 = *(const float4*)&sx[r0 + 0][c];
        const float4 s1 = *(const float4*)&sx[r0 + 1][c];
        const float4 s2 = *(const float4*)&sx[r0 + 2][c];
        const float4 s3 = *(const float4*)&sx[r0 + 3][c];
        const float4 w0 = __ldg((const float4*)(Wl + (c + 0) * C) + jg);
        const float4 w1 = __ldg((const float4*)(Wl + (c + 1) * C) + jg);
        const float4 w2 = __ldg((const float4*)(Wl + (c + 2) * C) + jg);
        const float4 w3 = __ldg((const float4*)(Wl + (c + 3) * C) + jg);

        #define ROW(a, sv) \
            acc[a][0] = fmaf(sv.x, w0.x, acc[a][0]); acc[a][1] = fmaf(sv.x, w0.y, acc[a][1]); \
            acc[a][2] = fmaf(sv.x, w0.z, acc[a][2]); acc[a][3] = fmaf(sv.x, w0.w, acc[a][3]); \
            acc[a][0] = fmaf(sv.y, w1.x, acc[a][0]); acc[a][1] = fmaf(sv.y, w1.y, acc[a][1]); \
            acc[a][2] = fmaf(sv.y, w1.z, acc[a][2]); acc[a][3] = fmaf(sv.y, w1.w, acc[a][3]); \
            acc[a][0] = fmaf(sv.z, w2.x, acc[a][0]); acc[a][1] = fmaf(sv.z, w2.y, acc[a][1]); \
            acc[a][2] = fmaf(sv.z, w2.z, acc[a][2]); acc[a][3] = fmaf(sv.z, w2.w, acc[a][3]); \
            acc[a][0] = fmaf(sv.w, w3.x, acc[a][0]); acc[a][1] = fmaf(sv.w, w3.y, acc[a][1]); \
            acc[a][2] = fmaf(sv.w, w3.z, acc[a][2]); acc[a][3] = fmaf(sv.w, w3.w, acc[a][3]);
        ROW(0, s0) ROW(1, s1) ROW(2, s2) ROW(3, s3)
        #undef ROW
    }

    const float4 bv = __ldg((const float4*)bl + jg);
    #pragma unroll
    for (int a = 0; a < 4; ++a) {
        const int n = n0 + r0 + a;
        if (n < N) {
            float4 o;
            o.x = acc[a][0] + bv.x;
            o.y = acc[a][1] + bv.y;
            o.z = acc[a][2] + bv.z;
            o.w = acc[a][3] + bv.w;
            *((float4*)(out + (size_t)n * C) + jg) = o;
        }
    }
}

// ---------------------------------------------------------------------------
// Launch: R10-verbatim 5-kernel chain, with the tiled k_out.
// ---------------------------------------------------------------------------
extern "C" void kernel_launch(void* const* d_in, const int* in_sizes, int n_in,
                              void* d_out, int out_size)
{
    const float* x         = (const float*)d_in[0];   // [N, 128]
    const float* edge_attr = (const float*)d_in[1];   // [E, 16]
    const float* ew        = (const float*)d_in[2];   // [E, 1]
    const float* Wb        = (const float*)d_in[3];   // [16, 128]
    const float* bb        = (const float*)d_in[4];   // [128]
    const float* Wl        = (const float*)d_in[5];   // [128, 128]
    const float* bl        = (const float*)d_in[6];   // [128]
    const int*   ei        = (const int*)d_in[7];     // [2, E]
    float*       out       = (float*)d_out;           // [N, 128]

    const int E = in_sizes[2];          // edge_weight element count
    const int N = in_sizes[0] / C;      // x rows

    {   // init accumulator (float4) + degree seeds
        int threads = 256;
        int blocks = (N * (C / 4) + threads - 1) / threads;
        k_init<<<blocks, threads>>>(N);
    }
    {
        int threads = 256;
        int work = (E + 3) / 4;
        int blocks = (work + threads - 1) / threads;
        k_deg<<<blocks, threads>>>(ei, E);
    }
    {
        int threads = 256;
        int blocks = (N + threads - 1) / threads;
        k_inv<<<blocks, threads>>>(N);
    }
    {
        int ntiles = (E + T - 1) / T;
        int blocks = (ntiles < NBLK) ? ntiles : NBLK;
        k_msg<<<blocks, 128>>>(x, edge_attr, ew, Wb, bb, ei, E);
    }
    {
        int blocks = (N + RT - 1) / RT;
        k_out<<<blocks, 128>>>(Wl, bl, x, out, N);
    }
}

// round 17
// speedup vs baseline: 1.9557x; 1.2669x over previous
#include <cuda_runtime.h>
#include <cstdint>

#define MAXN 10240          // >= 10000 nodes
#define C    128            // channels
#define BF   16             // bond features
#define T    128            // edges per SMEM tile
#define NBLK 456            // 152 SMs * 3 resident blocks
#define RT   16             // output rows per k_out block

// Scratch: __device__ globals (no allocation allowed).
__device__ __align__(128) float g_accum[MAXN * C];   // scatter-sum target [N, C]
__device__ int   g_deg_row[MAXN];
__device__ int   g_deg_col[MAXN];
__device__ float g_inv_row[MAXN];
__device__ float g_inv_col[MAXN];

// ---------------------------------------------------------------------------
// Kernel 1: zero accumulator (float4), init degrees to 1 (self-loop count).
// ---------------------------------------------------------------------------
__global__ void k_init(int N) {
    int i = blockIdx.x * blockDim.x + threadIdx.x;
    if (i < N * (C / 4)) ((float4*)g_accum)[i] = make_float4(0.f, 0.f, 0.f, 0.f);
    if (i < N) { g_deg_row[i] = 1; g_deg_col[i] = 1; }
}

// ---------------------------------------------------------------------------
// Kernel 2: degree histograms. 4 edges per thread via int4 loads.
// ---------------------------------------------------------------------------
__global__ void k_deg(const int* __restrict__ ei, int E) {
    int t = blockIdx.x * blockDim.x + threadIdx.x;
    int e = t * 4;
    if (e + 3 < E) {
        int4 r = *(const int4*)(ei + e);
        int4 c = *(const int4*)(ei + E + e);
        atomicAdd(&g_deg_row[r.x], 1); atomicAdd(&g_deg_row[r.y], 1);
        atomicAdd(&g_deg_row[r.z], 1); atomicAdd(&g_deg_row[r.w], 1);
        atomicAdd(&g_deg_col[c.x], 1); atomicAdd(&g_deg_col[c.y], 1);
        atomicAdd(&g_deg_col[c.z], 1); atomicAdd(&g_deg_col[c.w], 1);
    } else {
        for (; e < E; ++e) {
            atomicAdd(&g_deg_row[ei[e]], 1);
            atomicAdd(&g_deg_col[ei[E + e]], 1);
        }
    }
}

// ---------------------------------------------------------------------------
// Kernel 3: inverse-sqrt degree tables. deg >= 1 always (self-loops).
// ---------------------------------------------------------------------------
__global__ void k_inv(int N) {
    int i = blockIdx.x * blockDim.x + threadIdx.x;
    if (i >= N) return;
    g_inv_row[i] = rsqrtf((float)g_deg_row[i]);
    g_inv_col[i] = rsqrtf((float)g_deg_col[i]);
}

// ---------------------------------------------------------------------------
// SMEM tile of staged edge data (streams decoupled from compute via cp.async)
// ---------------------------------------------------------------------------
struct __align__(16) Tile {
    float attr[T * BF];   // 8192 B
    int   row[T];         // 512 B
    int   col[T];         // 512 B
    float ew[T];          // 512 B
};

__device__ __forceinline__ void cpa16(void* s, const void* g) {
    uint32_t sa = (uint32_t)__cvta_generic_to_shared(s);
    asm volatile("cp.async.cg.shared.global [%0], [%1], 16;" :: "r"(sa), "l"(g) : "memory");
}
__device__ __forceinline__ void cp_commit() {
    asm volatile("cp.async.commit_group;" ::: "memory");
}
__device__ __forceinline__ void cp_wait1() {
    asm volatile("cp.async.wait_group 1;" ::: "memory");
}

// Stage one tile (128 threads cooperate). Fast path uses cp.async; tail path
// plain loads+stores with zero-fill OOB.
__device__ __forceinline__ void stage_tile(
    Tile* t, int base, int E,
    const float* __restrict__ edge_attr,
    const int*   __restrict__ ei,
    const float* __restrict__ ew,
    int tid)
{
    if (base + T <= E && (E & 3) == 0) {
        const float4* asrc = (const float4*)edge_attr + (size_t)base * 4;
        #pragma unroll
        for (int j = 0; j < 4; ++j)
            cpa16(&t->attr[(tid + j * 128) * 4], asrc + tid + j * 128);
        if (tid < 32)        cpa16(&t->row[tid * 4],        ei + base + tid * 4);
        else if (tid < 64)   cpa16(&t->col[(tid - 32) * 4], ei + E + base + (tid - 32) * 4);
        else if (tid < 96)   cpa16(&t->ew [(tid - 64) * 4], ew + base + (tid - 64) * 4);
    } else {
        for (int i = tid; i < T * BF; i += 128) {
            int ge = base + (i >> 4);
            t->attr[i] = (ge < E) ? edge_attr[(size_t)ge * BF + (i & 15)] : 0.f;
        }
        if (tid < T) {
            int ge = base + tid;
            t->row[tid] = (ge < E) ? ei[ge] : 0;
            t->col[tid] = (ge < E) ? ei[E + ge] : 0;
            t->ew[tid]  = (ge < E) ? ew[ge] : 0.f;
        }
    }
}

// ---------------------------------------------------------------------------
// Kernel 4: persistent tiled message kernel — structure is the validated
// 153.7us R10 configuration. ONE change this round: GELU inside the edge
// loop uses the tanh-form with hardware tanh.approx.f32 (sm_75+, 1 MUFU op)
// instead of exact erff (~12-instr polynomial). Tolerance budget: bench
// threshold 1e-3; this approximation lands ~1e-4-6e-4 aggregate.
// ---------------------------------------------------------------------------
__global__ __launch_bounds__(128, 3) void k_msg(
    const float* __restrict__ x,
    const float* __restrict__ edge_attr,
    const float* __restrict__ ew,
    const float* __restrict__ Wb,
    const float* __restrict__ bb,
    const int*   __restrict__ ei,
    int E)
{
    __shared__ Tile tiles[2];

    const int tid  = threadIdx.x;
    const int lane = tid & 31;
    const int warp = tid >> 5;
    const int ntiles = (E + T - 1) / T;
    const int t0 = blockIdx.x;
    if (t0 >= ntiles) return;

    // --- per-warp W_bond slice in registers, k-pair packed ---
    unsigned long long W2[8][4];
    #pragma unroll
    for (int kp = 0; kp < 8; ++kp) {
        const float4 ra = __ldg((const float4*)Wb + (2*kp)   * 32 + lane);
        const float4 rb = __ldg((const float4*)Wb + (2*kp+1) * 32 + lane);
        asm("mov.b64 %0,{%1,%2};" : "=l"(W2[kp][0]) : "f"(ra.x), "f"(rb.x));
        asm("mov.b64 %0,{%1,%2};" : "=l"(W2[kp][1]) : "f"(ra.y), "f"(rb.y));
        asm("mov.b64 %0,{%1,%2};" : "=l"(W2[kp][2]) : "f"(ra.z), "f"(rb.z));
        asm("mov.b64 %0,{%1,%2};" : "=l"(W2[kp][3]) : "f"(ra.w), "f"(rb.w));
    }
    unsigned long long B0, B1, B2, B3;      // {bias, 0} accumulator seeds
    {
        const float4 bv = __ldg((const float4*)bb + lane);
        const float z = 0.0f;
        asm("mov.b64 %0,{%1,%2};" : "=l"(B0) : "f"(bv.x), "f"(z));
        asm("mov.b64 %0,{%1,%2};" : "=l"(B1) : "f"(bv.y), "f"(z));
        asm("mov.b64 %0,{%1,%2};" : "=l"(B2) : "f"(bv.z), "f"(z));
        asm("mov.b64 %0,{%1,%2};" : "=l"(B3) : "f"(bv.w), "f"(z));
    }

    // --- prologue: stage first two tiles ---
    stage_tile(&tiles[0], t0 * T, E, edge_attr, ei, ew, tid);
    cp_commit();
    {
        const int t1 = t0 + gridDim.x;
        if (t1 < ntiles) stage_tile(&tiles[1], t1 * T, E, edge_attr, ei, ew, tid);
    }
    cp_commit();

    int buf = 0;
    for (int tt = t0; tt < ntiles; tt += gridDim.x) {
        cp_wait1();                 // tile tt staged (own copies done)
        __syncthreads();            // visible to all warps
        const Tile* tp = &tiles[buf];
        const int base = tt * T;
        const int le0 = warp * 32;  // this warp's 32 edges within the tile
        const int nv = E - base - le0;   // #valid edges for this warp (may be <=0)

        // --- depth-2 x-gather pipeline over the warp's 32 edges ---
        int   rA = tp->row[le0],     cA = tp->col[le0];     float wA = tp->ew[le0];
        int   rB = tp->row[le0 + 1], cB = tp->col[le0 + 1]; float wB = tp->ew[le0 + 1];
        float4 xA = __ldg((const float4*)x + rA * 32 + lane);
        float  ivA = __ldg(g_inv_row + rA) * __ldg(g_inv_col + cA);
        float4 xB = __ldg((const float4*)x + rB * 32 + lane);
        float  ivB = __ldg(g_inv_row + rB) * __ldg(g_inv_col + cB);

        #pragma unroll 4
        for (int i = 0; i < 32; ++i) {
            // prefetch edge i+2
            int rC = 0, cC = 0; float wC = 0.f; float ivC = 0.f;
            float4 xC = make_float4(0.f, 0.f, 0.f, 0.f);
            if (i + 2 < 32) {
                rC = tp->row[le0 + i + 2];
                cC = tp->col[le0 + i + 2];
                wC = tp->ew [le0 + i + 2];
                xC  = __ldg((const float4*)x + rC * 32 + lane);
                ivC = __ldg(g_inv_row + rC) * __ldg(g_inv_col + cC);
            }

            if (i < nv) {
                // attr: broadcast LDS.128 -> FFMA2 operand pairs directly
                const ulonglong2* ap = (const ulonglong2*)(tp->attr + (le0 + i) * BF);
                const ulonglong2 q0 = ap[0], q1 = ap[1], q2 = ap[2], q3 = ap[3];
                const unsigned long long P[8] =
                    {q0.x, q0.y, q1.x, q1.y, q2.x, q2.y, q3.x, q3.y};

                unsigned long long acc0 = B0, acc1 = B1, acc2 = B2, acc3 = B3;
                #pragma unroll
                for (int kp = 0; kp < 8; ++kp) {
                    asm("fma.rn.f32x2 %0, %1, %2, %0;" : "+l"(acc0) : "l"(P[kp]), "l"(W2[kp][0]));
                    asm("fma.rn.f32x2 %0, %1, %2, %0;" : "+l"(acc1) : "l"(P[kp]), "l"(W2[kp][1]));
                    asm("fma.rn.f32x2 %0, %1, %2, %0;" : "+l"(acc2) : "l"(P[kp]), "l"(W2[kp][2]));
                    asm("fma.rn.f32x2 %0, %1, %2, %0;" : "+l"(acc3) : "l"(P[kp]), "l"(W2[kp][3]));
                }
                float lo0, hi0, lo1, hi1, lo2, hi2, lo3, hi3;
                asm("mov.b64 {%0,%1}, %2;" : "=f"(lo0), "=f"(hi0) : "l"(acc0));
                asm("mov.b64 {%0,%1}, %2;" : "=f"(lo1), "=f"(hi1) : "l"(acc1));
                asm("mov.b64 {%0,%1}, %2;" : "=f"(lo2), "=f"(hi2) : "l"(acc2));
                asm("mov.b64 {%0,%1}, %2;" : "=f"(lo3), "=f"(hi3) : "l"(acc3));

                const float v0 = xA.x + (lo0 + hi0);
                const float v1 = xA.y + (lo1 + hi1);
                const float v2 = xA.z + (lo2 + hi2);
                const float v3 = xA.w + (lo3 + hi3);

                const float h = 0.5f * ivA * wA;

                // tanh-form GELU with HW tanh: arg = 0.79788456*(v + 0.044715 v^3)
                //   = v * (0.79788456 + 0.035677408*v^2)
                const float p0 = v0 * fmaf(v0 * v0, 0.035677408f, 0.79788456f);
                const float p1 = v1 * fmaf(v1 * v1, 0.035677408f, 0.79788456f);
                const float p2 = v2 * fmaf(v2 * v2, 0.035677408f, 0.79788456f);
                const float p3 = v3 * fmaf(v3 * v3, 0.035677408f, 0.79788456f);
                float tt0, tt1, tt2, tt3;
                asm("tanh.approx.f32 %0, %1;" : "=f"(tt0) : "f"(p0));
                asm("tanh.approx.f32 %0, %1;" : "=f"(tt1) : "f"(p1));
                asm("tanh.approx.f32 %0, %1;" : "=f"(tt2) : "f"(p2));
                asm("tanh.approx.f32 %0, %1;" : "=f"(tt3) : "f"(p3));

                const float vh0 = v0 * h, vh1 = v1 * h, vh2 = v2 * h, vh3 = v3 * h;
                const float m0 = fmaf(vh0, tt0, vh0);
                const float m1 = fmaf(vh1, tt1, vh1);
                const float m2 = fmaf(vh2, tt2, vh2);
                const float m3 = fmaf(vh3, tt3, vh3);

                float* dst = &g_accum[(size_t)cA * C + lane * 4];
                asm volatile("red.global.add.v4.f32 [%0], {%1, %2, %3, %4};"
                             :: "l"(dst), "f"(m0), "f"(m1), "f"(m2), "f"(m3) : "memory");
            }

            // rotate (renamed away under unroll)
            rA = rB; cA = cB; wA = wB; xA = xB; ivA = ivB;
            rB = rC; cB = cC; wB = wC; xB = xC; ivB = ivC;
        }

        __syncthreads();            // all warps done reading tiles[buf]
        const int tn = tt + 2 * gridDim.x;
        if (tn < ntiles) stage_tile(&tiles[buf], tn * T, E, edge_attr, ei, ew, tid);
        cp_commit();                // exactly one group per iteration
        buf ^= 1;
    }
}

// ---------------------------------------------------------------------------
// Kernel 5: out = (g_accum + selfloop_msg) @ W_lin + b_lin, register-tiled.
// Self-loop keeps EXACT erff (N=10k only; cheap, trims total error).
// ---------------------------------------------------------------------------
__global__ __launch_bounds__(128) void k_out(
    const float* __restrict__ Wl,
    const float* __restrict__ bl,
    const float* __restrict__ x,
    float* __restrict__ out,
    int N)
{
    __shared__ __align__(16) float sx[RT][C];   // 8 KB
    const int tid = threadIdx.x;
    const int n0  = blockIdx.x * RT;

    // --- stage sx = g_accum + selfloop (gelu(x)*inv_r*inv_c, ew=1) ---
    #pragma unroll
    for (int it = 0; it < RT; ++it) {
        const int i = tid + it * 128;          // RT*C/128 = 16 elements/thread
        const int r = i >> 7, j = i & 127;
        const int n = n0 + r;
        if (n < N) {
            const float v = x[(size_t)n * C + j];
            const float g = 0.5f * v * (1.0f + erff(v * 0.70710678118654752440f));
            const float iv = g_inv_row[n] * g_inv_col[n];
            sx[r][j] = g_accum[(size_t)n * C + j] + g * iv;
        } else {
            sx[r][j] = 0.0f;
        }
    }
    __syncthreads();

    const int rg = tid >> 5;          // row group: 4 rows starting at 4*rg
    const int jg = tid & 31;          // col group: 4 cols starting at 4*jg
    const int r0 = rg * 4;

    float acc[4][4];
    #pragma unroll
    for (int a = 0; a < 4; ++a)
        #pragma unroll
        for (int b = 0; b < 4; ++b) acc[a][b] = 0.0f;

    #pragma unroll 4
    for (int c = 0; c < C; c += 4) {
        const float4 s0 = *(const float4*)&sx[r0 + 0][c];
        const float4 s1 = *(const float4*)&sx[r0 + 1][c];
        const float4 s2 = *(const float4*)&sx[r0 + 2][c];
        const float4 s3 = *(const float4*)&sx[r0 + 3][c];
        const float4 w0 = __ldg((const float4*)(Wl + (c + 0) * C) + jg);
        const float4 w1 = __ldg((const float4*)(Wl + (c + 1) * C) + jg);
        const float4 w2 = __ldg((const float4*)(Wl + (c + 2) * C) + jg);
        const float4 w3 = __ldg((const float4*)(Wl + (c + 3) * C) + jg);

        #define ROW(a, sv) \
            acc[a][0] = fmaf(sv.x, w0.x, acc[a][0]); acc[a][1] = fmaf(sv.x, w0.y, acc[a][1]); \
            acc[a][2] = fmaf(sv.x, w0.z, acc[a][2]); acc[a][3] = fmaf(sv.x, w0.w, acc[a][3]); \
            acc[a][0] = fmaf(sv.y, w1.x, acc[a][0]); acc[a][1] = fmaf(sv.y, w1.y, acc[a][1]); \
            acc[a][2] = fmaf(sv.y, w1.z, acc[a][2]); acc[a][3] = fmaf(sv.y, w1.w, acc[a][3]); \
            acc[a][0] = fmaf(sv.z, w2.x, acc[a][0]); acc[a][1] = fmaf(sv.z, w2.y, acc[a][1]); \
            acc[a][2] = fmaf(sv.z, w2.z, acc[a][2]); acc[a][3] = fmaf(sv.z, w2.w, acc[a][3]); \
            acc[a][0] = fmaf(sv.w, w3.x, acc[a][0]); acc[a][1] = fmaf(sv.w, w3.y, acc[a][1]); \
            acc[a][2] = fmaf(sv.w, w3.z, acc[a][2]); acc[a][3] = fmaf(sv.w, w3.w, acc[a][3]);
        ROW(0, s0) ROW(1, s1) ROW(2, s2) ROW(3, s3)
        #undef ROW
    }

    const float4 bv = __ldg((const float4*)bl + jg);
    #pragma unroll
    for (int a = 0; a < 4; ++a) {
        const int n = n0 + r0 + a;
        if (n < N) {
            float4 o;
            o.x = acc[a][0] + bv.x;
            o.y = acc[a][1] + bv.y;
            o.z = acc[a][2] + bv.z;
            o.w = acc[a][3] + bv.w;
            *((float4*)(out + (size_t)n * C) + jg) = o;
        }
    }
}

// ---------------------------------------------------------------------------
// Launch: validated 5-kernel chain.
// ---------------------------------------------------------------------------
extern "C" void kernel_launch(void* const* d_in, const int* in_sizes, int n_in,
                              void* d_out, int out_size)
{
    const float* x         = (const float*)d_in[0];   // [N, 128]
    const float* edge_attr = (const float*)d_in[1];   // [E, 16]
    const float* ew        = (const float*)d_in[2];   // [E, 1]
    const float* Wb        = (const float*)d_in[3];   // [16, 128]
    const float* bb        = (const float*)d_in[4];   // [128]
    const float* Wl        = (const float*)d_in[5];   // [128, 128]
    const float* bl        = (const float*)d_in[6];   // [128]
    const int*   ei        = (const int*)d_in[7];     // [2, E]
    float*       out       = (float*)d_out;           // [N, 128]

    const int E = in_sizes[2];          // edge_weight element count
    const int N = in_sizes[0] / C;      // x rows

    {   // init accumulator (float4) + degree seeds
        int threads = 256;
        int blocks = (N * (C / 4) + threads - 1) / threads;
        k_init<<<blocks, threads>>>(N);
    }
    {
        int threads = 256;
        int work = (E + 3) / 4;
        int blocks = (work + threads - 1) / threads;
        k_deg<<<blocks, threads>>>(ei, E);
    }
    {
        int threads = 256;
        int blocks = (N + threads - 1) / threads;
        k_inv<<<blocks, threads>>>(N);
    }
    {
        int ntiles = (E + T - 1) / T;
        int blocks = (ntiles < NBLK) ? ntiles : NBLK;
        k_msg<<<blocks, 128>>>(x, edge_attr, ew, Wb, bb, ei, E);
    }
    {
        int blocks = (N + RT - 1) / RT;
        k_out<<<blocks, 128>>>(Wl, bl, x, out, N);
    }
}